// round 1
// baseline (speedup 1.0000x reference)
#include <cuda_runtime.h>

#define Bsz   512
#define Hdim  100
#define Gdim  400
#define T_IN  1000
#define T_TOT 1300
#define NB    4
#define NCTA  128
#define NTHR  512

// Transposed weight scratch (written once per launch by prologue kernel).
__device__ float g_W1T[Hdim*Gdim];   // W_hh1^T  [k][g]
__device__ float g_W2iT[Hdim*Gdim];  // W_ih2^T  [k][g]
__device__ float g_W2hT[Hdim*Gdim];  // W_hh2^T  [k][g]

__global__ void transpose_weights(const float* __restrict__ W_hh1,
                                  const float* __restrict__ W_ih2,
                                  const float* __restrict__ W_hh2) {
    int i = blockIdx.x * blockDim.x + threadIdx.x;
    if (i >= Hdim * Gdim) return;
    int g = i / Hdim, k = i % Hdim;          // reads coalesced over i
    g_W1T [k*Gdim + g] = W_hh1[i];
    g_W2iT[k*Gdim + g] = W_ih2[i];
    g_W2hT[k*Gdim + g] = W_hh2[i];
}

__device__ __forceinline__ float sigf(float x) {
    return __fdividef(1.0f, 1.0f + __expf(-x));
}
__device__ __forceinline__ float tanha(float x) {
    // tanh(x) = 2*sigmoid(2x) - 1 ; saturates correctly for |x| large
    return fmaf(2.0f, sigf(2.0f * x), -1.0f);
}

__global__ __launch_bounds__(NTHR, 1)
void lstm2_kernel(const float* __restrict__ input,
                  const float* __restrict__ W_ih1,
                  const float* __restrict__ b_ih1,
                  const float* __restrict__ b_hh1,
                  const float* __restrict__ b_ih2,
                  const float* __restrict__ b_hh2,
                  const float* __restrict__ W_lin,
                  const float* __restrict__ b_lin,
                  float* __restrict__ out)
{
    extern __shared__ float sm[];
    float4* h1p   = (float4*)sm;              // [100] h1 packed over 4 batches
    float4* h2p   = h1p + Hdim;               // [100]
    float4* gates = h2p + Hdim;               // [400] per-gate, 4 batches
    float*  W1s   = (float*)(gates + Gdim);   // [40000] W_hh1^T resident
    float*  b1s   = W1s + Hdim*Gdim;          // [400]
    float*  b2s   = b1s + Gdim;               // [400]
    float*  wi1s  = b2s + Gdim;               // [400]
    float*  wlin  = wi1s + Gdim;              // [100]
    float*  xs    = wlin + Hdim;              // [4]
    float*  ys    = xs + 4;                   // [4]
    float*  blin  = ys + 4;                   // [1]

    const int tid = threadIdx.x;
    const int b0  = blockIdx.x * NB;

    // One-time init
    for (int i = tid; i < Hdim*Gdim; i += NTHR) W1s[i] = g_W1T[i];
    for (int i = tid; i < Gdim; i += NTHR) {
        b1s[i]  = b_ih1[i] + b_hh1[i];
        b2s[i]  = b_ih2[i] + b_hh2[i];
        wi1s[i] = W_ih1[i];
    }
    if (tid < Hdim) {
        wlin[tid] = W_lin[tid];
        h1p[tid] = make_float4(0.f, 0.f, 0.f, 0.f);
        h2p[tid] = make_float4(0.f, 0.f, 0.f, 0.f);
    }
    if (tid == 0) blin[0] = b_lin[0];
    __syncthreads();

    // Cell-role mapping (threads < 400): batch cb, hidden index cj.
    float c1 = 0.f, c2 = 0.f;
    const int cb = tid / Hdim;
    const int cj = tid % Hdim;

    for (int t = 0; t < T_TOT; ++t) {
        // x for this step: teacher-forced input, then autoregressive y
        if (tid < NB) xs[tid] = (t < T_IN) ? input[(b0 + tid)*T_IN + t] : ys[tid];
        __syncthreads();

        // ---- Layer 1 gates: g = x*W_ih1 + h1@W_hh1^T + b1 ----
        if (tid < Gdim) {
            const int g = tid;
            const float wi = wi1s[g];
            const float bb = b1s[g];
            float a0 = fmaf(xs[0], wi, bb);
            float a1 = fmaf(xs[1], wi, bb);
            float a2 = fmaf(xs[2], wi, bb);
            float a3 = fmaf(xs[3], wi, bb);
            const float* wp = W1s + g;
            #pragma unroll 4
            for (int k = 0; k < Hdim; ++k) {
                const float  w = wp[k*Gdim];      // coalesced, conflict-free
                const float4 h = h1p[k];          // broadcast
                a0 = fmaf(w, h.x, a0);
                a1 = fmaf(w, h.y, a1);
                a2 = fmaf(w, h.z, a2);
                a3 = fmaf(w, h.w, a3);
            }
            gates[g] = make_float4(a0, a1, a2, a3);
        }
        __syncthreads();

        // ---- Layer 1 cell update (c1 lives in registers) ----
        if (tid < Gdim) {
            const float* gp = (const float*)gates;
            const float vi = gp[(cj         )*4 + cb];
            const float vf = gp[(cj +   Hdim)*4 + cb];
            const float vg = gp[(cj + 2*Hdim)*4 + cb];
            const float vo = gp[(cj + 3*Hdim)*4 + cb];
            c1 = fmaf(sigf(vf), c1, sigf(vi) * tanha(vg));
            ((float*)(h1p + cj))[cb] = sigf(vo) * tanha(c1);
        }
        __syncthreads();

        // ---- Layer 2 gates: g = h1@W_ih2^T + h2@W_hh2^T + b2 (weights from L2) ----
        if (tid < Gdim) {
            const int g = tid;
            const float bb = b2s[g];
            float a0 = bb, a1 = bb, a2 = bb, a3 = bb;
            const float* w2i = g_W2iT + g;
            #pragma unroll 4
            for (int k = 0; k < Hdim; ++k) {
                const float  w = __ldg(w2i + k*Gdim);
                const float4 h = h1p[k];
                a0 = fmaf(w, h.x, a0);
                a1 = fmaf(w, h.y, a1);
                a2 = fmaf(w, h.z, a2);
                a3 = fmaf(w, h.w, a3);
            }
            const float* w2h = g_W2hT + g;
            #pragma unroll 4
            for (int k = 0; k < Hdim; ++k) {
                const float  w = __ldg(w2h + k*Gdim);
                const float4 h = h2p[k];
                a0 = fmaf(w, h.x, a0);
                a1 = fmaf(w, h.y, a1);
                a2 = fmaf(w, h.z, a2);
                a3 = fmaf(w, h.w, a3);
            }
            gates[g] = make_float4(a0, a1, a2, a3);
        }
        __syncthreads();

        // ---- Layer 2 cell update ----
        if (tid < Gdim) {
            const float* gp = (const float*)gates;
            const float vi = gp[(cj         )*4 + cb];
            const float vf = gp[(cj +   Hdim)*4 + cb];
            const float vg = gp[(cj + 2*Hdim)*4 + cb];
            const float vo = gp[(cj + 3*Hdim)*4 + cb];
            c2 = fmaf(sigf(vf), c2, sigf(vi) * tanha(vg));
            ((float*)(h2p + cj))[cb] = sigf(vo) * tanha(c2);
        }
        __syncthreads();

        // ---- Output projection: y[b] = h2[b]·W_lin + b_lin (one warp per batch) ----
        if (tid < 128) {
            const int w = tid >> 5, l = tid & 31;
            float s = 0.f;
            for (int j = l; j < Hdim; j += 32)
                s = fmaf(((const float*)(h2p + j))[w], wlin[j], s);
            #pragma unroll
            for (int o = 16; o > 0; o >>= 1)
                s += __shfl_down_sync(0xffffffffu, s, o);
            if (l == 0) {
                const float y = s + blin[0];
                out[(b0 + w)*T_TOT + t] = y;
                ys[w] = y;
            }
        }
        __syncthreads();
    }
}

extern "C" void kernel_launch(void* const* d_in, const int* in_sizes, int n_in,
                              void* d_out, int out_size) {
    const float* input = (const float*)d_in[0];
    const float* W_ih1 = (const float*)d_in[1];
    const float* W_hh1 = (const float*)d_in[2];
    const float* b_ih1 = (const float*)d_in[3];
    const float* b_hh1 = (const float*)d_in[4];
    const float* W_ih2 = (const float*)d_in[5];
    const float* W_hh2 = (const float*)d_in[6];
    const float* b_ih2 = (const float*)d_in[7];
    const float* b_hh2 = (const float*)d_in[8];
    const float* W_lin = (const float*)d_in[9];
    const float* b_lin = (const float*)d_in[10];
    float* out = (float*)d_out;

    transpose_weights<<<(Hdim*Gdim + 255)/256, 256>>>(W_hh1, W_ih2, W_hh2);

    const int smem_bytes = (int)((2400 + Hdim*Gdim + 3*Gdim + Hdim + 16) * sizeof(float));
    cudaFuncSetAttribute(lstm2_kernel,
                         cudaFuncAttributeMaxDynamicSharedMemorySize, smem_bytes);
    lstm2_kernel<<<NCTA, NTHR, smem_bytes>>>(input, W_ih1, b_ih1, b_hh1,
                                             b_ih2, b_hh2, W_lin, b_lin, out);
}